// round 17
// baseline (speedup 1.0000x reference)
#include <cuda_runtime.h>

// SIR recurrence, round 15: 3-chain / 6-cyc-floor body, overhead shaving.
//     r' = fma(-(1-K), w, r)
//     w' = fma(g, w, A*B)          <- stored; s0 = w * (1/A)
//     g' = fma(-w, g, r')
// Deltas vs R14 (math identical):
//   - 96-step straight-line bodies (24 x GROUP4, ~5KB, fits 6KB L0 I$)
//   - warp 4 (producer's SMSP partner) is barrier-only idle; consumers are
//     warps 1-3,5-7 (192 threads): producer SMSP has no competing issue
//   - CH=576 = 6 bodies exactly; last chunk 319 via leftover loops

#define CH        576            // 192 consumer threads * 3 rows; 576 = 96*6
#define NCH       4              // ceil(2047 / 576)
#define MAX_STEPS 2048

#define NB_ARRIVE(id, cnt) \
    asm volatile("bar.arrive %0, %1;" :: "r"(id), "r"(cnt) : "memory")
#define NB_SYNC(id, cnt) \
    asm volatile("bar.sync %0, %1;" :: "r"(id), "r"(cnt) : "memory")

// one step: advances (r, w, g), writes w into dst
#define STEP(dst)  do {                         \
        const float rn = fmaf(nK1, w, r);       \
        const float wn = fmaf(g,   w, AB);      \
        const float gn = fmaf(-w,  g, rn);      \
        (dst) = wn;                             \
        r = rn; w = wn; g = gn;                 \
    } while (0)

// 4 steps + one STS.128 at float4 index j
#define GROUP4(v, j)  do {                      \
        float4 b4;                              \
        STEP(b4.x); STEP(b4.y);                 \
        STEP(b4.z); STEP(b4.w);                 \
        (v)[j] = b4;                            \
    } while (0)

#define BODY24(v)  do {                                             \
        GROUP4(v, 0);  GROUP4(v, 1);  GROUP4(v, 2);  GROUP4(v, 3);  \
        GROUP4(v, 4);  GROUP4(v, 5);  GROUP4(v, 6);  GROUP4(v, 7);  \
        GROUP4(v, 8);  GROUP4(v, 9);  GROUP4(v, 10); GROUP4(v, 11); \
        GROUP4(v, 12); GROUP4(v, 13); GROUP4(v, 14); GROUP4(v, 15); \
        GROUP4(v, 16); GROUP4(v, 17); GROUP4(v, 18); GROUP4(v, 19); \
        GROUP4(v, 20); GROUP4(v, 21); GROUP4(v, 22); GROUP4(v, 23); \
    } while (0)

__global__ void __launch_bounds__(256, 1)
sir_kernel(const float* __restrict__ x,
           const float* __restrict__ w2p,
           const float* __restrict__ w3p,
           const float* __restrict__ b3p,
           const float* __restrict__ w4p,
           float* __restrict__ out,
           int n)
{
    __shared__ __align__(16) float s0buf[MAX_STEPS];  // w_i = A*s0_i (or s0_i)
    __shared__ float wpart[8];

    const int tid   = threadIdx.x;
    const int wid   = tid >> 5;
    const int steps = n - 1;            // 2047

    const float w2 = *w2p, w3 = *w3p, b3 = *b3p, w4 = *w4p;
    const float w2sq = w2 * w2;
    const float w4sq = w4 * w4;
    const float K    = 1.0f - w2sq - w4sq;
    const float oneK = w2sq + w4sq;     // 1 - K
    const float A    = w3 * w3 * 1.0e-3f;
    const float B    = fmaf(w3, b3, b3);
    const bool  wmode = fabsf(A) > 1e-20f;          // uniform across block
    const float scale = wmode ? (1.0f / A) : 1.0f;  // s0 = buf * scale

    if (wid == 0) {
        // ------------- producer: warp 0 (alone on its SMSP with idle warp 4) -------------
        const float h0 = fmaf(A, x[0] + x[2], K);   // K + A*u0
        float w = A * x[0];
        float g = h0 - w;
        float r = h0 - A * B;
        const float AB  = A * B;
        const float nK1 = -oneK;

        // fallback state (R11 body, for |A| ~ 0)
        float s0f = x[0];
        float hf  = h0;
        const float negA = -A;
        const float negE = -(A * oneK);

        int done = 0;
        for (int c = 0; c < NCH; ++c) {
            const int end = (done + CH < steps) ? done + CH : steps;
            if (tid == 0) {
                if (wmode) {
                    const int ngrp  = (end - done) >> 2;   // full 4-groups
                    const int nbody = ngrp / 24;           // 96-step bodies
                    float4* v = reinterpret_cast<float4*>(s0buf + done);
                    for (int b = 0; b < nbody; ++b, v += 24)
                        BODY24(v);
                    int i = done + nbody * 96;
                    for (; i + 4 <= end; i += 4) {
                        float4 b4;
                        STEP(b4.x); STEP(b4.y); STEP(b4.z); STEP(b4.w);
                        *reinterpret_cast<float4*>(s0buf + i) = b4;
                    }
                    for (; i < end; ++i) {
                        const float rn = fmaf(nK1, w, r);
                        const float wn = fmaf(g,  w, AB);
                        const float gn = fmaf(-w, g, rn);
                        s0buf[i] = wn;
                        r = rn; w = wn; g = gn;
                    }
                } else {
                    #pragma unroll 16
                    for (int i = done; i < end; ++i) {
                        const float gg = fmaf(negA, s0f, hf);
                        const float t  = fmaf(s0f, gg, B);
                        hf  = fmaf(negE, s0f, hf);
                        s0f = t;
                        s0buf[i] = s0f;
                    }
                }
            }
            done = end;
            __syncwarp();
            NB_ARRIVE(c + 1, 256);       // whole warp, convergent
        }
    } else if (wid == 4) {
        // ------------- idle warp on producer's SMSP: barrier bookkeeping only -------------
        for (int c = 0; c < NCH; ++c)
            NB_ARRIVE(c + 1, 256);       // whole warp, convergent
    } else {
        // ------------- consumers: warps 1-3, 5-7 (192 threads) -------------
        const int      cw   = (wid > 4) ? (wid - 2) : (wid - 1);  // 0..5
        const unsigned lane = tid & 31u;
        const int      ctid = cw * 32 + (int)lane;                // 0..191

        const float x0 = x[0], x1 = x[1], x3 = x[3];
        const float base2 = x[2] + K * x0;       // x2 + K*x0
        const float noneK = -oneK;

        float carry = 0.0f;

        for (int c = 0; c < NCH; ++c) {
            NB_SYNC(c + 1, 256);                 // wait for producer chunk c

            const int r0 = c * CH + ctid * 3;
            float v0 = (r0     < steps) ? s0buf[r0]     * scale : 0.0f;
            float v1 = (r0 + 1 < steps) ? s0buf[r0 + 1] * scale : 0.0f;
            float v2 = (r0 + 2 < steps) ? s0buf[r0 + 2] * scale : 0.0f;

            const float l1  = v0 + v1;
            const float run = l1 + v2;

            float scan = run;
            #pragma unroll
            for (int off = 1; off < 32; off <<= 1) {
                const float o = __shfl_up_sync(0xffffffffu, scan, off);
                if (lane >= off) scan += o;
            }
            if (lane == 31) wpart[cw] = scan;
            NB_SYNC(15, 192);                    // consumer-internal, convergent

            float woff = 0.0f, chtot = 0.0f;
            #pragma unroll
            for (int w = 0; w < 6; ++w) {
                const float pv = wpart[w];
                chtot += pv;
                if (w < cw) woff += pv;
            }

            float Qexc = carry + woff + (scan - run);

            #pragma unroll
            for (int k = 0; k < 3; ++k) {
                const int r = r0 + k;
                const float s0v = (k == 0) ? v0 : (k == 1) ? v1 : v2;
                if (r < steps) {
                    const float S = x0 + Qexc;
                    float* o = out + 5 * r;
                    o[0] = s0v;
                    o[1] = fmaf(w2sq, S, x1);
                    o[2] = fmaf(noneK, Qexc, base2 - s0v);
                    o[3] = fmaf(w4sq, S, x3);
                    o[4] = 0.0f;
                }
                Qexc += s0v;
            }

            carry += chtot;
        }
    }
}

extern "C" void kernel_launch(void* const* d_in, const int* in_sizes, int n_in,
                              void* d_out, int out_size)
{
    const float* x  = (const float*)d_in[0];
    const float* w2 = (const float*)d_in[1];
    const float* w3 = (const float*)d_in[2];
    const float* b3 = (const float*)d_in[3];
    const float* w4 = (const float*)d_in[4];
    float* out = (float*)d_out;

    const int n = out_size / 5 + 1;   // out_size = (n-1)*5

    sir_kernel<<<1, 256>>>(x, w2, w3, b3, w4, out, n);
}